// round 13
// baseline (speedup 1.0000x reference)
#include <cuda_runtime.h>
#include <cuda_bf16.h>
#include <cstdint>
#include <cstdio>

// ---------------- problem constants ----------------
#define BATCH   64
#define DIMS    200
#define SIZEM   50
#define NUMQ    10000
#define LBERT   512
#define HBERT   768

#define OFF_P   0
#define OFF_MV  (BATCH*DIMS)
#define OFF_W   (OFF_MV + BATCH*(DIMS+1)*SIZEM*DIMS)

// ---------------- scratch ----------------
__device__ uint2 g_T1  [BATCH*DIMS*(LBERT/2)];   // packed T1t
__device__ uint2 g_emat[BATCH*DIMS*(DIMS/2)];    // packed em_at
__device__ uint2 g_k   [BATCH*DIMS*(DIMS/2)];    // packed k
__device__ uint2 g_v   [BATCH*DIMS*(DIMS/2)];    // packed v
__device__ float g_e   [BATCH*DIMS*DIMS];
__device__ float g_a   [BATCH*DIMS*DIMS];
__device__ uint2 g_read[BATCH*DIMS*(DIMS/2)];    // packed read
__device__ float g_f   [BATCH*DIMS*DIMS];
__device__ float g_fl  [BATCH*DIMS*DIMS];
__device__ float g_p2  [BATCH*4*DIMS];

// precomputed bf16 hi/lo weights, NEW layout [ch16][n(200)][4]{bh0,bh1,bl0,bl1}
__device__ uint4 g_pw_at [48*200*4];
__device__ uint4 g_pw_at2[32*200*4];
__device__ uint4 g_pw_e  [13*200*4];
__device__ uint4 g_pw_a  [13*200*4];
__device__ uint4 g_pw_f  [25*200*4];
__device__ uint4 g_pw_fus[25*200*4];

// ---------------- streams/events ----------------
struct StreamPack {
    cudaStream_t sB;
    cudaEvent_t evFork, evB, evA2, evFl;
    StreamPack() {
        cudaStreamCreateWithFlags(&sB, cudaStreamNonBlocking);
        cudaEventCreateWithFlags(&evFork, cudaEventDisableTiming);
        cudaEventCreateWithFlags(&evB,   cudaEventDisableTiming);
        cudaEventCreateWithFlags(&evA2,  cudaEventDisableTiming);
        cudaEventCreateWithFlags(&evFl,  cudaEventDisableTiming);
    }
};
static StreamPack g_sp;

// ================= low-level helpers =================
__device__ __forceinline__ void cp16(uint32_t saddr, const void* g) {
    asm volatile("cp.async.cg.shared.global [%0], [%1], 16;" :: "r"(saddr), "l"(g));
}
__device__ __forceinline__ void cp8(uint32_t saddr, const void* g) {
    asm volatile("cp.async.ca.shared.global [%0], [%1], 8;" :: "r"(saddr), "l"(g));
}
#define CP_COMMIT asm volatile("cp.async.commit_group;" ::: "memory")
#define CP_WAIT(n) asm volatile("cp.async.wait_group %0;" :: "n"(n) : "memory")

__device__ __forceinline__ void mma16816(float* c, const uint32_t* a, uint32_t b0, uint32_t b1) {
    asm volatile("mma.sync.aligned.m16n8k16.row.col.f32.bf16.bf16.f32 "
        "{%0,%1,%2,%3}, {%4,%5,%6,%7}, {%8,%9}, {%0,%1,%2,%3};"
        : "+f"(c[0]), "+f"(c[1]), "+f"(c[2]), "+f"(c[3])
        : "r"(a[0]), "r"(a[1]), "r"(a[2]), "r"(a[3]), "r"(b0), "r"(b1));
}

__device__ __forceinline__ void split2(float x, float y, uint32_t& hi, uint32_t& lo) {
    uint32_t h;
    asm("cvt.rn.bf16x2.f32 %0, %1, %2;" : "=r"(h) : "f"(y), "f"(x));
    float hx = __uint_as_float(h << 16);
    float hy = __uint_as_float(h & 0xffff0000u);
    float rx = x - hx, ry = y - hy;
    uint32_t l;
    asm("cvt.rn.bf16x2.f32 %0, %1, %2;" : "=r"(l) : "f"(ry), "f"(rx));
    hi = h; lo = l;
}

// ---------------- merged weight precompute: K16 chunks ----------------
__global__ void prep_all(const float* __restrict__ W0, const float* __restrict__ W1,
                         const float* __restrict__ W2, const float* __restrict__ W3,
                         const float* __restrict__ W4, const float* __restrict__ W5,
                         uint4* __restrict__ o0, uint4* __restrict__ o1,
                         uint4* __restrict__ o2, uint4* __restrict__ o3,
                         uint4* __restrict__ o4, uint4* __restrict__ o5)
{
    int idx = blockIdx.x * 256 + threadIdx.x;
    const int segNC[6] = {48, 32, 13, 13, 25, 25};
    const int segK [6] = {HBERT, LBERT, DIMS, DIMS, 2*DIMS, 2*DIMS};
    const float* Ws[6] = {W0, W1, W2, W3, W4, W5};
    uint4* os[6] = {o0, o1, o2, o3, o4, o5};

    int s2 = -1;
    #pragma unroll
    for (int t2 = 0; t2 < 6; ++t2) {
        if (s2 < 0) {
            int cnt = segNC[t2] * 800;
            if (idx < cnt) s2 = t2;
            else           idx -= cnt;
        }
    }
    if (s2 < 0) return;

    const int K = segK[s2];
    const float* W = Ws[s2];
    int sub = idx & 3;
    int n   = (idx >> 2) % 200;
    int ch  = idx / 800;
    int k   = ch * 16 + 2 * sub;
    const float* Wr = W + (size_t)n * K;
    float x0 = (k     < K) ? Wr[k]     : 0.f;
    float x1 = (k + 1 < K) ? Wr[k + 1] : 0.f;
    float x2 = (k + 8 < K) ? Wr[k + 8] : 0.f;
    float x3 = (k + 9 < K) ? Wr[k + 9] : 0.f;
    uint32_t h0, l0, h1, l1;
    split2(x0, x1, h0, l0);
    split2(x2, x3, h1, l1);
    uint4 v; v.x = h0; v.y = h1; v.z = l0; v.w = l1;
    os[s2][idx] = v;
}

// ================= mma.sync bf16-split SGEMM: K16 chunks, 4-stage ring =================
#define SA_W   20                                  // words per A row (16 used + pad)
#define SB_W   20                                  // words per B n-row (16 used + pad)
#define ASTG   (128*SA_W*4)                        // 10240
#define BSTG   (104*SB_W*4)                        // 8320
#define SM_BIAS 0
#define SM_A    1024
#define SM_B    (SM_A + 4*ASTG)                    // 41984
#define GEMM_SMEM (SM_B + 4*BSTG)                  // 75264

__device__ __forceinline__ void load_tileA16(const float* __restrict__ A, int K, int Ksplit,
                                             int bm, int kstart, float* Afp, int tid)
{
    // fp32 A, no split usage beyond bounds (Ksplit==K for T1)
    if (kstart + 16 <= K) {
        const float* base = A + (size_t)bm * K + kstart;
        uint32_t sb = (uint32_t)__cvta_generic_to_shared(Afp);
        #pragma unroll
        for (int pass = 0; pass < 2; ++pass) {
            int idx = tid + pass * 256;
            int row = idx >> 2, c4 = idx & 3;
            cp16(sb + (uint32_t)(row * SA_W + c4 * 4) * 4, base + (size_t)row * K + c4 * 4);
        }
    } else {
        for (int idx = tid; idx < 2048; idx += 256) {
            int row = idx >> 4, kk = idx & 15;
            int k = kstart + kk;
            Afp[row * SA_W + kk] = (k < K) ? A[(size_t)(bm + row) * K + k] : 0.f;
        }
    }
}

// packed A tile: 128 rows x 8 pairs; Kp/Kps in PAIRS; chunk kp0 = ch*8
__device__ __forceinline__ void load_tileAp16(const uint2* __restrict__ A,
                                              const uint2* __restrict__ A2,
                                              int Kp, int Kps, int bm, int kp0,
                                              uint2* Aps, int tid)
{
    bool f1 = (kp0 + 8 <= Kps);
    bool f2 = (kp0 >= Kps) && (kp0 + 8 <= Kp);
    if (f1 || f2) {
        const uint2* base = f1 ? (A + (size_t)bm * Kps + kp0)
                               : (A2 + (size_t)bm * (Kp - Kps) + (kp0 - Kps));
        size_t rs = f1 ? (size_t)Kps : (size_t)(Kp - Kps);
        uint32_t sb = (uint32_t)__cvta_generic_to_shared(Aps);
        #pragma unroll
        for (int pass = 0; pass < 2; ++pass) {
            int idx = tid + pass * 256;
            int row = idx >> 2, c = idx & 3;           // 4 chunks of 16B (2 pairs)
            cp16(sb + (uint32_t)(row * SA_W + c * 4) * 4, base + (size_t)row * rs + c * 2);
        }
    } else {
        int K2 = Kp - Kps;
        for (int idx = tid; idx < 1024; idx += 256) {
            int row = idx >> 3, pp = idx & 7;
            int kp = kp0 + pp;
            uint2 v = make_uint2(0u, 0u);
            if (kp < Kps)      v = A[(size_t)(bm + row) * Kps + kp];
            else if (kp < Kp)  v = A2[(size_t)(bm + row) * K2 + (kp - Kps)];
            Aps[row * (SA_W / 2) + pp] = v;
        }
    }
}

__device__ __forceinline__ void load_tileB16(const uint4* __restrict__ pw, int ch, int n0,
                                             int nrows, uint32_t* Bsm, int tid)
{
    uint32_t sb = (uint32_t)__cvta_generic_to_shared(Bsm);
    const uint4* src = pw + ((size_t)ch * 200 + n0) * 4;
    int total = nrows * 4;
    for (int idx = tid; idx < total; idx += 256) {
        int n = idx >> 2, sub = idx & 3;
        cp16(sb + (uint32_t)(n * SB_W + sub * 4) * 4, src + (size_t)n * 4 + sub);
    }
}

// MODE: 0 packed-out, 2 tanh, 3 relu, 4 packed transposed-T1, 5 dual (z0 sig, z1 tanh)
// APK: 0 fp32 A, 1 packed A
template<int MODE, int APK>
__global__ void __launch_bounds__(256, 2)
tgemm(const void* __restrict__ Av, const void* __restrict__ A2v,
      const uint4* __restrict__ pwa, const uint4* __restrict__ pwb,
      const float* __restrict__ biasa, const float* __restrict__ biasb,
      float* __restrict__ Ca, float* __restrict__ Cb,
      int K, int Ksplit, int NC)
{
    extern __shared__ char smem[];
    float* biasS = (float*)(smem + SM_BIAS);

    const int tid  = threadIdx.x;
    const int wid  = tid >> 5;
    const int lane = tid & 31;
    const int gid  = lane >> 2;
    const int tig  = lane & 3;
    const int warpM = wid * 16;

    const int n0  = blockIdx.y * 104;
    const int NFr = (blockIdx.y == 0) ? 13 : 12;
    const int bm  = blockIdx.x * 128;

    const uint4* pw = pwa;
    const float* bs = biasa;
    float* C = Ca;
    bool second = false;
    if (MODE == 5 && blockIdx.z == 1) { pw = pwb; bs = biasb; C = Cb; second = true; }

    for (int i = tid; i < 200; i += 256) biasS[i] = bs[i];

    const float* Af  = (const float*)Av;
    const uint2* Ap  = (const uint2*)Av;
    const uint2* A2p = (const uint2*)A2v;
    const int Kp = K / 2, Kps = Ksplit / 2;

    #define ABUF(s) ((float*)(smem + SM_A + (s) * ASTG))
    #define APBUF(s) ((uint2*)(smem + SM_A + (s) * ASTG))
    #define BBUF(s) ((uint32_t*)(smem + SM_B + (s) * BSTG))

    // preload 3 stages
    #pragma unroll
    for (int s = 0; s < 3; ++s) {
        if (s < NC) {
            if (APK == 0) load_tileA16(Af, K, Ksplit, bm, s * 16, ABUF(s), tid);
            else          load_tileAp16(Ap, A2p, Kp, Kps, bm, s * 8, APBUF(s), tid);
            load_tileB16(pw, s, n0, NFr * 8, BBUF(s), tid);
        }
        CP_COMMIT;
    }

    float c[13][4];
    #pragma unroll
    for (int i = 0; i < 13; ++i) { c[i][0] = 0.f; c[i][1] = 0.f; c[i][2] = 0.f; c[i][3] = 0.f; }

    for (int ch = 0; ch < NC; ++ch) {
        CP_WAIT(2);
        __syncthreads();
        if (ch + 3 < NC) {
            int s = (ch + 3) & 3;
            if (APK == 0) load_tileA16(Af, K, Ksplit, bm, (ch + 3) * 16, ABUF(s), tid);
            else          load_tileAp16(Ap, A2p, Kp, Kps, bm, (ch + 3) * 8, APBUF(s), tid);
            load_tileB16(pw, ch + 3, n0, NFr * 8, BBUF(s), tid);
        }
        CP_COMMIT;

        const int cs = ch & 3;
        uint32_t ah[4], al[4];
        if (APK == 0) {
            const float* Acur = ABUF(cs);
            #pragma unroll
            for (int i = 0; i < 4; ++i) {
                int rr = warpM + gid + (i & 1) * 8;
                int kk = 2 * tig + ((i >> 1) * 8);
                float2 v = *(const float2*)&Acur[rr * SA_W + kk];
                split2(v.x, v.y, ah[i], al[i]);
            }
        } else {
            const uint2* Apc = APBUF(cs);
            #pragma unroll
            for (int i = 0; i < 4; ++i) {
                int rr = warpM + gid + (i & 1) * 8;
                int kp = tig + ((i >> 1) * 4);
                uint2 v = Apc[rr * (SA_W / 2) + kp];
                ah[i] = v.x; al[i] = v.y;
            }
        }
        const uint32_t* Bcur = BBUF(cs);
        #pragma unroll
        for (int nf = 0; nf < 13; ++nf) {
            if (nf < NFr) {
                const uint4 bv = *(const uint4*)&Bcur[(nf * 8 + gid) * SB_W + tig * 4];
                mma16816(c[nf], ah, bv.x, bv.y);
                mma16816(c[nf], ah, bv.z, bv.w);
                mma16816(c[nf], al, bv.x, bv.y);
            }
        }
    }
    __syncthreads();

    // ---- bias in registers ----
    #pragma unroll
    for (int nf = 0; nf < 13; ++nf) {
        if (nf >= NFr) break;
        int n = n0 + nf * 8 + 2 * tig;
        float b0v = biasS[n], b1v = biasS[n + 1];
        c[nf][0] += b0v; c[nf][1] += b1v;
        c[nf][2] += b0v; c[nf][3] += b1v;
    }

    // ---------------- epilogue ----------------
    if (MODE == 4) {
        float* stg = (float*)(smem + SM_A);
        uint2* Cp  = (uint2*)C;
        const int b   = bm >> 9;
        const int lb0 = bm & 511;
        const int l   = warpM + gid;
        #pragma unroll
        for (int h = 0; h < 2; ++h) {
            const int nfStart = h * 7;
            const int nfEnd   = (NFr < nfStart + 7) ? NFr : (nfStart + 7);
            __syncthreads();
            #pragma unroll
            for (int nf = 0; nf < 13; ++nf) {
                if (nf >= nfStart && nf < nfEnd) {
                    int nn = (nf - nfStart) * 8 + 2 * tig;
                    stg[nn * 132 + l]           = c[nf][0];
                    stg[(nn + 1) * 132 + l]     = c[nf][1];
                    stg[nn * 132 + l + 8]       = c[nf][2];
                    stg[(nn + 1) * 132 + l + 8] = c[nf][3];
                }
            }
            __syncthreads();
            const int nrows  = (nfEnd - nfStart) * 8;
            const int total4 = nrows * 32;
            for (int idx = tid; idx < total4; idx += 256) {
                int rr = idx >> 5, c4 = idx & 31;
                float4 v = *(float4*)&stg[rr * 132 + c4 * 4];
                uint32_t h0, w0, h1, w1;
                split2(v.x, v.y, h0, w0);
                split2(v.z, v.w, h1, w1);
                uint4 o; o.x = h0; o.y = w0; o.z = h1; o.w = w1;
                *(uint4*)&Cp[((size_t)b * 200 + n0 + nfStart * 8 + rr) * 256 + (lb0 >> 1) + c4 * 2] = o;
            }
        }
        return;
    }

    const int m0 = bm + warpM + gid;
    if (MODE == 0) {
        uint2* Cp = (uint2*)C;
        #pragma unroll
        for (int nf = 0; nf < 13; ++nf) {
            if (nf >= NFr) break;
            int n = n0 + nf * 8 + 2 * tig;
            uint32_t hw, lw;
            split2(c[nf][0], c[nf][1], hw, lw);
            Cp[(size_t)m0 * 100 + (n >> 1)] = make_uint2(hw, lw);
            split2(c[nf][2], c[nf][3], hw, lw);
            Cp[(size_t)(m0 + 8) * 100 + (n >> 1)] = make_uint2(hw, lw);
        }
        return;
    }

    #pragma unroll
    for (int nf = 0; nf < 13; ++nf) {
        if (nf >= NFr) break;
        int n = n0 + nf * 8 + 2 * tig;
        float v00 = c[nf][0], v01 = c[nf][1];
        float v10 = c[nf][2], v11 = c[nf][3];
        if (MODE == 2) {
            v00 = tanhf(v00); v01 = tanhf(v01); v10 = tanhf(v10); v11 = tanhf(v11);
        } else if (MODE == 3) {
            v00 = fmaxf(v00, 0.f); v01 = fmaxf(v01, 0.f);
            v10 = fmaxf(v10, 0.f); v11 = fmaxf(v11, 0.f);
        } else if (MODE == 5) {
            if (second) { v00 = tanhf(v00); v01 = tanhf(v01); v10 = tanhf(v10); v11 = tanhf(v11); }
            else {
                v00 = 1.f / (1.f + expf(-v00)); v01 = 1.f / (1.f + expf(-v01));
                v10 = 1.f / (1.f + expf(-v10)); v11 = 1.f / (1.f + expf(-v11));
            }
        }
        float2 lo2 = {v00, v01}, hi2 = {v10, v11};
        *(float2*)&C[(size_t)m0 * 200 + n] = lo2;
        *(float2*)&C[(size_t)(m0 + 8) * 200 + n] = hi2;
    }
}

// ---------------- wk + packed k/v gather ----------------
__global__ void wk_gather_kernel(const int* __restrict__ q, const int* __restrict__ rr,
                                 const float* __restrict__ k_emb, const float* __restrict__ v_emb,
                                 const float* __restrict__ Mk,
                                 float* __restrict__ wOut, uint2* __restrict__ kpk,
                                 uint2* __restrict__ vpk)
{
    int m   = blockIdx.x;
    int tid = threadIdx.x;                 // 256
    __shared__ float krow[DIMS];
    __shared__ float part4[200];
    __shared__ float logits[SIZEM];
    __shared__ float sm_max, sm_sum;

    int qi = q[m];
    if (tid < 100) {
        float2 kf = *(const float2*)&k_emb[(size_t)qi * DIMS + 2 * tid];
        krow[2 * tid] = kf.x; krow[2 * tid + 1] = kf.y;
        uint32_t hw, lw;
        split2(kf.x, kf.y, hw, lw);
        kpk[(size_t)m * 100 + tid] = make_uint2(hw, lw);
        int x = qi + NUMQ * rr[m];
        float2 vf = *(const float2*)&v_emb[(size_t)x * DIMS + 2 * tid];
        split2(vf.x, vf.y, hw, lw);
        vpk[(size_t)m * 100 + tid] = make_uint2(hw, lw);
    }
    __syncthreads();

    if (tid < 200) {
        int s = tid >> 2, g = tid & 3;
        const float* mk = Mk + s * DIMS + g * 50;
        const float* kr = krow + g * 50;
        float acc = 0.f;
        #pragma unroll 10
        for (int kk = 0; kk < 50; ++kk) acc = fmaf(kr[kk], __ldg(&mk[kk]), acc);
        part4[tid] = acc;
    }
    __syncthreads();
    if (tid < SIZEM)
        logits[tid] = part4[4 * tid] + part4[4 * tid + 1] + part4[4 * tid + 2] + part4[4 * tid + 3];
    __syncthreads();
    if (tid < 32) {
        float v = logits[tid];
        if (tid + 32 < SIZEM) v = fmaxf(v, logits[tid + 32]);
        #pragma unroll
        for (int o = 16; o > 0; o >>= 1) v = fmaxf(v, __shfl_xor_sync(0xffffffff, v, o));
        if (tid == 0) sm_max = v;
    }
    __syncthreads();
    if (tid < SIZEM) logits[tid] = expf(logits[tid] - sm_max);
    __syncthreads();
    if (tid < 32) {
        float v = (tid < SIZEM) ? logits[tid] : 0.f;
        if (tid + 32 < SIZEM) v += logits[tid + 32];
        #pragma unroll
        for (int o = 16; o > 0; o >>= 1) v += __shfl_xor_sync(0xffffffff, v, o);
        if (tid == 0) sm_sum = v;
    }
    __syncthreads();
    if (tid < SIZEM) wOut[(size_t)m * SIZEM + tid] = logits[tid] / sm_sum;
}

// ---------------- memory scan: float4 states, cp.async ring ----------------
// grid (2, 64), 256 threads. tid<250: sg = tid/25 (10 groups of 5 s), jq = tid%25, j = 4*jq.
__global__ void __launch_bounds__(256)
scan_kernel(const float* __restrict__ w,
            const float* __restrict__ e,
            const float* __restrict__ a,
            const float* __restrict__ Mv0,
            float* __restrict__ MvOut,
            uint2* __restrict__ readPk)
{
    const int cs = blockIdx.x;            // 0..1
    const int b  = blockIdx.y;
    const int j0 = cs * 100;
    __shared__ __align__(16) float ebuf[4][100];
    __shared__ __align__(16) float abuf[4][100];
    __shared__ __align__(16) float wbuf[4][52];
    __shared__ __align__(16) float part[2][1000];
    const int tid = threadIdx.x;          // 256

    const int sg = tid / 25;              // 0..9 for tid<250
    const int jq = tid % 25;
    const int s0 = sg * 5;

    float4 st[5];
    if (tid < 250) {
        #pragma unroll
        for (int i = 0; i < 5; ++i)
            st[i] = *(const float4*)&Mv0[(s0 + i) * DIMS + j0 + 4 * jq];
    }

    #define SCAN_STAGE(tt) do {                                                         \
        int _slot = (tt) & 3;                                                           \
        if (tid < 25) {                                                                 \
            cp16((uint32_t)__cvta_generic_to_shared(&ebuf[_slot][tid * 4]),             \
                 e + ((size_t)b * DIMS + (tt)) * DIMS + j0 + tid * 4);                  \
        } else if (tid < 50) {                                                          \
            int _q = tid - 25;                                                          \
            cp16((uint32_t)__cvta_generic_to_shared(&abuf[_slot][_q * 4]),              \
                 a + ((size_t)b * DIMS + (tt)) * DIMS + j0 + _q * 4);                   \
        } else if (tid < 75) {                                                          \
            int _q = tid - 50;                                                          \
            cp8((uint32_t)__cvta_generic_to_shared(&wbuf[_slot][_q * 2]),               \
                w + ((size_t)b * DIMS + (tt)) * SIZEM + _q * 2);                        \
        }                                                                               \
    } while (0)

    SCAN_STAGE(0); CP_COMMIT;
    SCAN_STAGE(1); CP_COMMIT;

    for (int t = 0; t < DIMS; ++t) {
        const int cur = t & 3;
        if (t + 2 < DIMS) SCAN_STAGE(t + 2);
        CP_COMMIT;
        CP_WAIT(2);
        __syncthreads();

        if (tid < 250) {
            float4 ev = *(const float4*)&ebuf[cur][4 * jq];
            float4 av = *(const float4*)&abuf[cur][4 * jq];
            float4 acc = {0.f, 0.f, 0.f, 0.f};
            float* outb = MvOut + ((size_t)(b * (DIMS + 1) + t) * SIZEM) * DIMS + j0 + 4 * jq;
            #pragma unroll
            for (int i = 0; i < 5; ++i) {
                float wv = wbuf[cur][s0 + i];
                float4 m = st[i];
                *(float4*)(outb + (size_t)(s0 + i) * DIMS) = m;     // emit pre-update
                acc.x = fmaf(wv, m.x, acc.x); acc.y = fmaf(wv, m.y, acc.y);
                acc.z = fmaf(wv, m.z, acc.z); acc.w = fmaf(wv, m.w, acc.w);
                st[i].x = fmaf(wv, fmaf(-ev.x, m.x, av.x), m.x);
                st[i].y = fmaf(wv, fmaf(-ev.y, m.y, av.y), m.y);
                st[i].z = fmaf(wv, fmaf(-ev.z, m.z, av.z), m.z);
                st[i].w = fmaf(wv, fmaf(-ev.w, m.w, av.w), m.w);
            }
            *(float4*)&part[t & 1][sg * 100 + 4 * jq] = acc;
        }
        if (t > 0 && tid < 25) {
            const float* pv = part[(t - 1) & 1];
            float4 s = {0.f, 0.f, 0.f, 0.f};
            #pragma unroll
            for (int g = 0; g < 10; ++g) {
                float4 p4 = *(const float4*)&pv[g * 100 + 4 * tid];
                s.x += p4.x; s.y += p4.y; s.z += p4.z; s.w += p4.w;
            }
            uint32_t h0, l0, h1, l1;
            split2(s.x, s.y, h0, l0);
            split2(s.z, s.w, h1, l1);
            uint4 o; o.x = h0; o.y = l0; o.z = h1; o.w = l1;
            *(uint4*)&readPk[((size_t)b * DIMS + (t - 1)) * 100 + (j0 >> 1) + 2 * tid] = o;
        }
    }
    __syncthreads();
    if (tid < 25) {
        const float* pv = part[199 & 1];
        float4 s = {0.f, 0.f, 0.f, 0.f};
        #pragma unroll
        for (int g = 0; g < 10; ++g) {
            float4 p4 = *(const float4*)&pv[g * 100 + 4 * tid];
            s.x += p4.x; s.y += p4.y; s.z += p4.z; s.w += p4.w;
        }
        uint32_t h0, l0, h1, l1;
        split2(s.x, s.y, h0, l0);
        split2(s.z, s.w, h1, l1);
        uint4 o; o.x = h0; o.y = l0; o.z = h1; o.w = l1;
        *(uint4*)&readPk[((size_t)b * DIMS + 199) * 100 + (j0 >> 1) + 2 * tid] = o;
    }
    if (tid < 250) {
        #pragma unroll
        for (int i = 0; i < 5; ++i)
            *(float4*)&MvOut[((size_t)(b * (DIMS + 1) + DIMS) * SIZEM + s0 + i) * DIMS + j0 + 4 * jq] = st[i];
    }
    #undef SCAN_STAGE
}

// ---------------- p2 partials ----------------
__global__ void p2_kernel(const float* __restrict__ fl, const float* __restrict__ Wp,
                          float* __restrict__ p2part)
{
    int b = blockIdx.x, part = blockIdx.y;
    int t = threadIdx.x;
    if (t >= DIMS) return;
    const float* base = fl + (size_t)b * DIMS * DIMS + (size_t)part * 50 * DIMS + t;
    const float* wp = Wp + DIMS + part * 50;
    float a0 = 0.f, a1 = 0.f;
    #pragma unroll
    for (int c = 0; c < 50; c += 2) {
        a0 = fmaf(__ldg(&wp[c]),     base[(size_t)c * DIMS],       a0);
        a1 = fmaf(__ldg(&wp[c + 1]), base[(size_t)(c + 1) * DIMS], a1);
    }
    p2part[((size_t)b * 4 + part) * DIMS + t] = a0 + a1;
}

// ---------------- final p ----------------
__global__ void p_kernel(const float* __restrict__ f, const float* __restrict__ p2part,
                         const float* __restrict__ Wp, const float* __restrict__ bp,
                         float* __restrict__ pOut)
{
    int bt = blockIdx.x;
    int b  = bt / DIMS, t = bt % DIMS;
    int tid = threadIdx.x;                // 128
    float acc = 0.f;
    for (int c = tid; c < DIMS; c += 128)
        acc = fmaf(__ldg(&Wp[c]), f[(size_t)bt * DIMS + c], acc);
    __shared__ float red[128];
    red[tid] = acc;
    __syncthreads();
    #pragma unroll
    for (int s = 64; s > 0; s >>= 1) {
        if (tid < s) red[tid] += red[tid + s];
        __syncthreads();
    }
    if (tid == 0) {
        float p2 = p2part[((size_t)b * 4 + 0) * DIMS + t] + p2part[((size_t)b * 4 + 1) * DIMS + t]
                 + p2part[((size_t)b * 4 + 2) * DIMS + t] + p2part[((size_t)b * 4 + 3) * DIMS + t];
        pOut[bt] = 1.f / (1.f + expf(-(red[0] + p2 + bp[0])));
    }
}

// ---------------- launcher ----------------
extern "C" void kernel_launch(void* const* d_in, const int* in_sizes, int n_in,
                              void* d_out, int out_size)
{
    const int*   q     = (const int*)d_in[0];
    const int*   r     = (const int*)d_in[1];
    const float* bert  = (const float*)d_in[2];
    const float* k_emb = (const float*)d_in[3];
    const float* v_emb = (const float*)d_in[4];
    const float* Mk    = (const float*)d_in[5];
    const float* Mv0   = (const float*)d_in[6];
    const float* W_at  = (const float*)d_in[7];
    const float* b_at  = (const float*)d_in[8];
    const float* W_at2 = (const float*)d_in[9];
    const float* b_at2 = (const float*)d_in[10];
    const float* W_fus = (const float*)d_in[11];
    const float* b_fus = (const float*)d_in[12];
    const float* W_e   = (const float*)d_in[13];
    const float* b_e   = (const float*)d_in[14];
    const float* W_a   = (const float*)d_in[15];
    const float* b_a   = (const float*)d_in[16];
    const float* W_f   = (const float*)d_in[17];
    const float* b_f   = (const float*)d_in[18];
    const float* W_p   = (const float*)d_in[19];
    const float* b_p   = (const float*)d_in[20];

    float* out    = (float*)d_out;
    float* p_out  = out + OFF_P;
    float* mv_out = out + OFF_MV;
    float* w_out  = out + OFF_W;

    uint2 *T1p, *ematp, *kp, *vp, *readp;
    float *eb, *ab, *fb, *flb, *p2b;
    cudaGetSymbolAddress((void**)&T1p,   g_T1);
    cudaGetSymbolAddress((void**)&ematp, g_emat);
    cudaGetSymbolAddress((void**)&kp,    g_k);
    cudaGetSymbolAddress((void**)&vp,    g_v);
    cudaGetSymbolAddress((void**)&eb,    g_e);
    cudaGetSymbolAddress((void**)&ab,    g_a);
    cudaGetSymbolAddress((void**)&readp, g_read);
    cudaGetSymbolAddress((void**)&fb,    g_f);
    cudaGetSymbolAddress((void**)&flb,   g_fl);
    cudaGetSymbolAddress((void**)&p2b,   g_p2);

    uint4 *pw_at, *pw_at2, *pw_e, *pw_a, *pw_f, *pw_fus;
    cudaGetSymbolAddress((void**)&pw_at,  g_pw_at);
    cudaGetSymbolAddress((void**)&pw_at2, g_pw_at2);
    cudaGetSymbolAddress((void**)&pw_e,   g_pw_e);
    cudaGetSymbolAddress((void**)&pw_a,   g_pw_a);
    cudaGetSymbolAddress((void**)&pw_f,   g_pw_f);
    cudaGetSymbolAddress((void**)&pw_fus, g_pw_fus);

    cudaFuncSetAttribute((const void*)tgemm<0,1>, cudaFuncAttributeMaxDynamicSharedMemorySize, GEMM_SMEM);
    cudaFuncSetAttribute((const void*)tgemm<2,1>, cudaFuncAttributeMaxDynamicSharedMemorySize, GEMM_SMEM);
    cudaFuncSetAttribute((const void*)tgemm<3,1>, cudaFuncAttributeMaxDynamicSharedMemorySize, GEMM_SMEM);
    cudaFuncSetAttribute((const void*)tgemm<4,0>, cudaFuncAttributeMaxDynamicSharedMemorySize, GEMM_SMEM);
    cudaFuncSetAttribute((const void*)tgemm<5,1>, cudaFuncAttributeMaxDynamicSharedMemorySize, GEMM_SMEM);

    const int MR = BATCH * DIMS;          // 12800
    cudaStream_t s0 = 0;
    cudaStream_t sB = g_sp.sB;

    // ---- prep all weights, then fork ----
    prep_all<<<488, 256, 0, s0>>>(W_at, W_at2, W_e, W_a, W_f, W_fus,
                                  pw_at, pw_at2, pw_e, pw_a, pw_f, pw_fus);
    cudaEventRecord(g_sp.evFork, s0);
    cudaStreamWaitEvent(sB, g_sp.evFork, 0);

    // ---- chain B on sB: wk/gather -> e,a ----
    wk_gather_kernel<<<MR, 256, 0, sB>>>(q, r, k_emb, v_emb, Mk, w_out, kp, vp);
    tgemm<5,1><<<dim3(100, 2, 2), 256, GEMM_SMEM, sB>>>(vp, nullptr, pw_e, pw_a, b_e, b_a,
                                                        eb, ab, DIMS, DIMS, 13);
    cudaEventRecord(g_sp.evB, sB);

    // ---- chain A on s0: T1 (fp32 A) -> em_at (packed A) ----
    tgemm<4,0><<<dim3(256, 2), 256, GEMM_SMEM, s0>>>(bert, nullptr, pw_at, nullptr, b_at, nullptr,
                                                     (float*)T1p, nullptr, HBERT, HBERT, 48);
    tgemm<0,1><<<dim3(100, 2), 256, GEMM_SMEM, s0>>>(T1p, nullptr, pw_at2, nullptr, b_at2, nullptr,
                                                     (float*)ematp, nullptr, LBERT, LBERT, 32);
    cudaEventRecord(g_sp.evA2, s0);

    // ---- sB: fl + p2 overlap with scan ----
    cudaStreamWaitEvent(sB, g_sp.evA2, 0);
    tgemm<3,1><<<dim3(100, 2), 256, GEMM_SMEM, sB>>>(vp, ematp, pw_fus, nullptr, b_fus, nullptr,
                                                     flb, nullptr, 2 * DIMS, DIMS, 25);
    p2_kernel<<<dim3(BATCH, 4), 256, 0, sB>>>(flb, W_p, p2b);
    cudaEventRecord(g_sp.evFl, sB);

    // ---- s0: scan (after e/a), then f, then p ----
    cudaStreamWaitEvent(s0, g_sp.evB, 0);
    scan_kernel<<<dim3(2, BATCH), 256, 0, s0>>>(w_out, eb, ab, Mv0, mv_out, readp);
    tgemm<2,1><<<dim3(100, 2), 256, GEMM_SMEM, s0>>>(readp, kp, pw_f, nullptr, b_f, nullptr,
                                                     fb, nullptr, 2 * DIMS, DIMS, 25);
    cudaStreamWaitEvent(s0, g_sp.evFl, 0);
    p_kernel<<<MR, 128, 0, s0>>>(fb, p2b, W_p, b_p, p_out);
}

// round 14
// speedup vs baseline: 1.1467x; 1.1467x over previous
#include <cuda_runtime.h>
#include <cuda_bf16.h>
#include <cstdint>
#include <cstdio>

// ---------------- problem constants ----------------
#define BATCH   64
#define DIMS    200
#define SIZEM   50
#define NUMQ    10000
#define LBERT   512
#define HBERT   768

#define OFF_P   0
#define OFF_MV  (BATCH*DIMS)
#define OFF_W   (OFF_MV + BATCH*(DIMS+1)*SIZEM*DIMS)

// ---------------- scratch ----------------
__device__ uint2 g_T1  [BATCH*DIMS*(LBERT/2)];   // packed T1t
__device__ uint2 g_emat[BATCH*DIMS*(DIMS/2)];    // packed em_at
__device__ uint2 g_k   [BATCH*DIMS*(DIMS/2)];    // packed k
__device__ uint2 g_v   [BATCH*DIMS*(DIMS/2)];    // packed v
__device__ float g_e   [BATCH*DIMS*DIMS];
__device__ float g_a   [BATCH*DIMS*DIMS];
__device__ uint2 g_read[BATCH*DIMS*(DIMS/2)];    // packed read
__device__ float g_f   [BATCH*DIMS*DIMS];
__device__ float g_fl  [BATCH*DIMS*DIMS];
__device__ float g_p2  [BATCH*4*DIMS];

// precomputed bf16 hi/lo weights, layout [ch][n(200)][8]{bh0,bh1,bl0,bl1}
__device__ uint4 g_pw_at [24*200*8];
__device__ uint4 g_pw_at2[16*200*8];
__device__ uint4 g_pw_e  [ 7*200*8];
__device__ uint4 g_pw_a  [ 7*200*8];
__device__ uint4 g_pw_f  [13*200*8];
__device__ uint4 g_pw_fus[13*200*8];

// ---------------- streams/events ----------------
struct StreamPack {
    cudaStream_t sB;
    cudaEvent_t evFork, evB, evA2, evFl;
    StreamPack() {
        cudaStreamCreateWithFlags(&sB, cudaStreamNonBlocking);
        cudaEventCreateWithFlags(&evFork, cudaEventDisableTiming);
        cudaEventCreateWithFlags(&evB,   cudaEventDisableTiming);
        cudaEventCreateWithFlags(&evA2,  cudaEventDisableTiming);
        cudaEventCreateWithFlags(&evFl,  cudaEventDisableTiming);
    }
};
static StreamPack g_sp;

// ================= low-level helpers =================
__device__ __forceinline__ void cp16(uint32_t saddr, const void* g) {
    asm volatile("cp.async.cg.shared.global [%0], [%1], 16;" :: "r"(saddr), "l"(g));
}
__device__ __forceinline__ void cp8(uint32_t saddr, const void* g) {
    asm volatile("cp.async.ca.shared.global [%0], [%1], 8;" :: "r"(saddr), "l"(g));
}
#define CP_COMMIT asm volatile("cp.async.commit_group;" ::: "memory")
#define CP_WAIT0  asm volatile("cp.async.wait_group 0;" ::: "memory")

__device__ __forceinline__ void mma16816(float* c, const uint32_t* a, uint32_t b0, uint32_t b1) {
    asm volatile("mma.sync.aligned.m16n8k16.row.col.f32.bf16.bf16.f32 "
        "{%0,%1,%2,%3}, {%4,%5,%6,%7}, {%8,%9}, {%0,%1,%2,%3};"
        : "+f"(c[0]), "+f"(c[1]), "+f"(c[2]), "+f"(c[3])
        : "r"(a[0]), "r"(a[1]), "r"(a[2]), "r"(a[3]), "r"(b0), "r"(b1));
}

__device__ __forceinline__ void split2(float x, float y, uint32_t& hi, uint32_t& lo) {
    uint32_t h;
    asm("cvt.rn.bf16x2.f32 %0, %1, %2;" : "=r"(h) : "f"(y), "f"(x));
    float hx = __uint_as_float(h << 16);
    float hy = __uint_as_float(h & 0xffff0000u);
    float rx = x - hx, ry = y - hy;
    uint32_t l;
    asm("cvt.rn.bf16x2.f32 %0, %1, %2;" : "=r"(l) : "f"(ry), "f"(rx));
    hi = h; lo = l;
}

// ---------------- merged weight precompute ----------------
__global__ void prep_all(const float* __restrict__ W0, const float* __restrict__ W1,
                         const float* __restrict__ W2, const float* __restrict__ W3,
                         const float* __restrict__ W4, const float* __restrict__ W5,
                         uint4* __restrict__ o0, uint4* __restrict__ o1,
                         uint4* __restrict__ o2, uint4* __restrict__ o3,
                         uint4* __restrict__ o4, uint4* __restrict__ o5)
{
    int idx = blockIdx.x * 256 + threadIdx.x;
    const int segNC[6] = {24, 16, 7, 7, 13, 13};
    const int segK [6] = {HBERT, LBERT, DIMS, DIMS, 2*DIMS, 2*DIMS};
    const float* Ws[6] = {W0, W1, W2, W3, W4, W5};
    uint4* os[6] = {o0, o1, o2, o3, o4, o5};

    int s2 = -1;
    #pragma unroll
    for (int t2 = 0; t2 < 6; ++t2) {
        if (s2 < 0) {
            int cnt = segNC[t2] * 1600;
            if (idx < cnt) s2 = t2;
            else           idx -= cnt;
        }
    }
    if (s2 < 0) return;

    const int K = segK[s2];
    const float* W = Ws[s2];
    int sub = idx & 7;
    int n   = (idx >> 3) % 200;
    int ch  = idx / 1600;
    int w0  = (sub >> 2) * 8 + (sub & 3);
    int k   = ch * 32 + 2 * w0;
    const float* Wr = W + (size_t)n * K;
    float x0 = (k     < K) ? Wr[k]     : 0.f;
    float x1 = (k + 1 < K) ? Wr[k + 1] : 0.f;
    float x2 = (k + 8 < K) ? Wr[k + 8] : 0.f;
    float x3 = (k + 9 < K) ? Wr[k + 9] : 0.f;
    uint32_t h0, l0, h1, l1;
    split2(x0, x1, h0, l0);
    split2(x2, x3, h1, l1);
    uint4 v; v.x = h0; v.y = h1; v.z = l0; v.w = l1;
    os[s2][idx] = v;
}

// ================= mma.sync bf16-split SGEMM (round-12 proven config) =================
// grid: (2, blocks_m, z) — n-split on X so the pair sharing a bm is wave-adjacent (L2 reuse)
#define SA_STRIDE 40
#define SAP_STRIDE 20
#define SBROW     48
#define SM_BIAS   0
#define SM_A      1024
#define SM_B      (SM_A + 2*128*SA_STRIDE*4)
#define GEMM_SMEM (SM_B + 2*104*SBROW*4)              // 81920

__device__ __forceinline__ void load_tileA(const float* __restrict__ A,
                                           int K, int bm, int kstart,
                                           float* Afp, int tid)
{
    if (kstart + 32 <= K) {
        const float* base = A + (size_t)bm * K + kstart;
        uint32_t sb = (uint32_t)__cvta_generic_to_shared(Afp);
        #pragma unroll
        for (int pass = 0; pass < 4; ++pass) {
            int idx = tid + pass * 256;
            int row = idx >> 3, c4 = idx & 7;
            cp16(sb + (uint32_t)(row * SA_STRIDE + c4 * 4) * 4, base + (size_t)row * K + c4 * 4);
        }
    } else {
        for (int idx = tid; idx < 4096; idx += 256) {
            int row = idx >> 5, kk = idx & 31;
            int k = kstart + kk;
            Afp[row * SA_STRIDE + kk] = (k < K) ? A[(size_t)(bm + row) * K + k] : 0.f;
        }
    }
}

__device__ __forceinline__ void load_tileAp(const uint2* __restrict__ A,
                                            const uint2* __restrict__ A2,
                                            int Kp, int Kps, int bm, int kp0,
                                            uint2* Aps, int tid)
{
    bool f1 = (kp0 + 16 <= Kps);
    bool f2 = (kp0 >= Kps) && (kp0 + 16 <= Kp);
    if (f1 || f2) {
        const uint2* base = f1 ? (A + (size_t)bm * Kps + kp0)
                               : (A2 + (size_t)bm * (Kp - Kps) + (kp0 - Kps));
        size_t rs = f1 ? (size_t)Kps : (size_t)(Kp - Kps);
        uint32_t sb = (uint32_t)__cvta_generic_to_shared(Aps);
        #pragma unroll
        for (int pass = 0; pass < 4; ++pass) {
            int idx = tid + pass * 256;
            int row = idx >> 3, c = idx & 7;
            cp16(sb + (uint32_t)(row * SAP_STRIDE + c * 2) * 8, base + (size_t)row * rs + c * 2);
        }
    } else {
        int K2 = Kp - Kps;
        for (int idx = tid; idx < 2048; idx += 256) {
            int row = idx >> 4, pp = idx & 15;
            int kp = kp0 + pp;
            uint2 v = make_uint2(0u, 0u);
            if (kp < Kps)      v = A[(size_t)(bm + row) * Kps + kp];
            else if (kp < Kp)  v = A2[(size_t)(bm + row) * K2 + (kp - Kps)];
            Aps[row * SAP_STRIDE + pp] = v;
        }
    }
}

__device__ __forceinline__ void load_tileB(const uint4* __restrict__ pw, int ch, int n0,
                                           int nrows, uint32_t* Bsm, int tid)
{
    uint32_t sb = (uint32_t)__cvta_generic_to_shared(Bsm);
    const uint4* src = pw + ((size_t)ch * 200 + n0) * 8;
    int total = nrows * 8;
    for (int idx = tid; idx < total; idx += 256) {
        int n = idx >> 3, sub = idx & 7;
        cp16(sb + (uint32_t)(n * SBROW + sub * 4) * 4, src + (size_t)n * 8 + sub);
    }
}

// MODE: 0 packed-out (em_at), 2 tanh, 3 relu, 4 packed transposed-T1, 5 dual (z0 sig, z1 tanh)
// APK: 0 = A fp32, 1 = A packed
template<int MODE, int APK>
__global__ void __launch_bounds__(256, 2)
tgemm(const void* __restrict__ Av, const void* __restrict__ A2v,
      const uint4* __restrict__ pwa, const uint4* __restrict__ pwb,
      const float* __restrict__ biasa, const float* __restrict__ biasb,
      float* __restrict__ Ca, float* __restrict__ Cb,
      int K, int Ksplit, int NC)
{
    extern __shared__ char smem[];
    float*    biasS = (float*)(smem + SM_BIAS);
    float*    Afp[2] = { (float*)(smem + SM_A), (float*)(smem + SM_A) + 128 * SA_STRIDE };
    uint2*    Aps[2] = { (uint2*)(smem + SM_A), (uint2*)(smem + SM_A) + 128 * SAP_STRIDE };
    uint32_t* Bsm[2] = { (uint32_t*)(smem + SM_B), (uint32_t*)(smem + SM_B) + 104 * SBROW };

    const int tid  = threadIdx.x;
    const int wid  = tid >> 5;
    const int lane = tid & 31;
    const int gid  = lane >> 2;
    const int tig  = lane & 3;
    const int warpM = wid * 16;

    // n-split on X (wave-adjacent pair shares bm -> A hits L2 on second block)
    const int n0  = blockIdx.x * 104;
    const int NFr = (blockIdx.x == 0) ? 13 : 12;
    const int bm  = blockIdx.y * 128;

    const uint4* pw = pwa;
    const float* bs = biasa;
    float* C = Ca;
    bool second = false;
    if (MODE == 5 && blockIdx.z == 1) { pw = pwb; bs = biasb; C = Cb; second = true; }

    for (int i = tid; i < 200; i += 256) biasS[i] = bs[i];

    const float* Af  = (const float*)Av;
    const uint2* Ap  = (const uint2*)Av;
    const uint2* A2p = (const uint2*)A2v;
    const int Kp = K / 2, Kps = Ksplit / 2;

    if (APK == 0) load_tileA(Af, K, bm, 0, Afp[0], tid);
    else          load_tileAp(Ap, A2p, Kp, Kps, bm, 0, Aps[0], tid);
    load_tileB(pw, 0, n0, NFr * 8, Bsm[0], tid);
    CP_COMMIT;
    CP_WAIT0;
    __syncthreads();

    float c[13][4];
    #pragma unroll
    for (int i = 0; i < 13; ++i) { c[i][0] = 0.f; c[i][1] = 0.f; c[i][2] = 0.f; c[i][3] = 0.f; }

    for (int ch = 0; ch < NC; ++ch) {
        const float* Acur  = Afp[ch & 1];
        const uint2* Apcur = Aps[ch & 1];
        const uint32_t* Bcur = Bsm[ch & 1];
        if (ch + 1 < NC) {
            if (APK == 0) load_tileA(Af, K, bm, (ch + 1) * 32, Afp[(ch + 1) & 1], tid);
            else          load_tileAp(Ap, A2p, Kp, Kps, bm, (ch + 1) * 16, Aps[(ch + 1) & 1], tid);
            load_tileB(pw, ch + 1, n0, NFr * 8, Bsm[(ch + 1) & 1], tid);
            CP_COMMIT;
        }
        #pragma unroll
        for (int st2 = 0; st2 < 2; ++st2) {
            uint32_t ah[4], al[4];
            if (APK == 0) {
                const int koff = st2 * 16;
                #pragma unroll
                for (int i = 0; i < 4; ++i) {
                    int rr = warpM + gid + (i & 1) * 8;
                    int kk = koff + 2 * tig + ((i >> 1) * 8);
                    float2 v = *(const float2*)&Acur[rr * SA_STRIDE + kk];
                    split2(v.x, v.y, ah[i], al[i]);
                }
            } else {
                const int kpo = st2 * 8;
                #pragma unroll
                for (int i = 0; i < 4; ++i) {
                    int rr = warpM + gid + (i & 1) * 8;
                    int kp = kpo + tig + ((i >> 1) * 4);
                    uint2 v = Apcur[rr * SAP_STRIDE + kp];
                    ah[i] = v.x; al[i] = v.y;
                }
            }
            #pragma unroll
            for (int nf = 0; nf < 13; ++nf) {
                if (nf < NFr) {
                    const uint4 bv = *(const uint4*)&Bcur[(nf * 8 + gid) * SBROW + st2 * 16 + tig * 4];
                    mma16816(c[nf], ah, bv.x, bv.y);
                    mma16816(c[nf], ah, bv.z, bv.w);
                    mma16816(c[nf], al, bv.x, bv.y);
                }
            }
        }
        if (ch + 1 < NC) {
            CP_WAIT0;
            __syncthreads();
        }
    }

    // ---- bias in registers ----
    #pragma unroll
    for (int nf = 0; nf < 13; ++nf) {
        if (nf >= NFr) break;
        int n = n0 + nf * 8 + 2 * tig;
        float b0v = biasS[n], b1v = biasS[n + 1];
        c[nf][0] += b0v; c[nf][1] += b1v;
        c[nf][2] += b0v; c[nf][3] += b1v;
    }

    // ---------------- epilogue ----------------
    if (MODE == 4) {
        float* stg = (float*)(smem + SM_A);
        uint2* Cp  = (uint2*)C;
        const int b   = bm >> 9;
        const int lb0 = bm & 511;
        const int l   = warpM + gid;
        #pragma unroll
        for (int h = 0; h < 2; ++h) {
            const int nfStart = h * 7;
            const int nfEnd   = (NFr < nfStart + 7) ? NFr : (nfStart + 7);
            __syncthreads();
            #pragma unroll
            for (int nf = 0; nf < 13; ++nf) {
                if (nf >= nfStart && nf < nfEnd) {
                    int nn = (nf - nfStart) * 8 + 2 * tig;
                    stg[nn * 132 + l]           = c[nf][0];
                    stg[(nn + 1) * 132 + l]     = c[nf][1];
                    stg[nn * 132 + l + 8]       = c[nf][2];
                    stg[(nn + 1) * 132 + l + 8] = c[nf][3];
                }
            }
            __syncthreads();
            const int nrows  = (nfEnd - nfStart) * 8;
            const int total4 = nrows * 32;
            for (int idx = tid; idx < total4; idx += 256) {
                int rr = idx >> 5, c4 = idx & 31;
                float4 v = *(float4*)&stg[rr * 132 + c4 * 4];
                uint32_t h0, w0, h1, w1;
                split2(v.x, v.y, h0, w0);
                split2(v.z, v.w, h1, w1);
                uint4 o; o.x = h0; o.y = w0; o.z = h1; o.w = w1;
                *(uint4*)&Cp[((size_t)b * 200 + n0 + nfStart * 8 + rr) * 256 + (lb0 >> 1) + c4 * 2] = o;
            }
        }
        return;
    }

    const int m0 = bm + warpM + gid;
    if (MODE == 0) {
        uint2* Cp = (uint2*)C;
        #pragma unroll
        for (int nf = 0; nf < 13; ++nf) {
            if (nf >= NFr) break;
            int n = n0 + nf * 8 + 2 * tig;
            uint32_t hw, lw;
            split2(c[nf][0], c[nf][1], hw, lw);
            Cp[(size_t)m0 * 100 + (n >> 1)] = make_uint2(hw, lw);
            split2(c[nf][2], c[nf][3], hw, lw);
            Cp[(size_t)(m0 + 8) * 100 + (n >> 1)] = make_uint2(hw, lw);
        }
        return;
    }

    #pragma unroll
    for (int nf = 0; nf < 13; ++nf) {
        if (nf >= NFr) break;
        int n = n0 + nf * 8 + 2 * tig;
        float v00 = c[nf][0], v01 = c[nf][1];
        float v10 = c[nf][2], v11 = c[nf][3];
        if (MODE == 2) {
            v00 = tanhf(v00); v01 = tanhf(v01); v10 = tanhf(v10); v11 = tanhf(v11);
        } else if (MODE == 3) {
            v00 = fmaxf(v00, 0.f); v01 = fmaxf(v01, 0.f);
            v10 = fmaxf(v10, 0.f); v11 = fmaxf(v11, 0.f);
        } else if (MODE == 5) {
            if (second) { v00 = tanhf(v00); v01 = tanhf(v01); v10 = tanhf(v10); v11 = tanhf(v11); }
            else {
                v00 = 1.f / (1.f + expf(-v00)); v01 = 1.f / (1.f + expf(-v01));
                v10 = 1.f / (1.f + expf(-v10)); v11 = 1.f / (1.f + expf(-v11));
            }
        }
        float2 lo2 = {v00, v01}, hi2 = {v10, v11};
        *(float2*)&C[(size_t)m0 * 200 + n] = lo2;
        *(float2*)&C[(size_t)(m0 + 8) * 200 + n] = hi2;
    }
}

// ---------------- wk + packed k/v gather ----------------
__global__ void wk_gather_kernel(const int* __restrict__ q, const int* __restrict__ rr,
                                 const float* __restrict__ k_emb, const float* __restrict__ v_emb,
                                 const float* __restrict__ Mk,
                                 float* __restrict__ wOut, uint2* __restrict__ kpk,
                                 uint2* __restrict__ vpk)
{
    int m   = blockIdx.x;
    int tid = threadIdx.x;                 // 256
    __shared__ float krow[DIMS];
    __shared__ float part4[200];
    __shared__ float logits[SIZEM];
    __shared__ float sm_max, sm_sum;

    int qi = q[m];
    if (tid < 100) {
        float2 kf = *(const float2*)&k_emb[(size_t)qi * DIMS + 2 * tid];
        krow[2 * tid] = kf.x; krow[2 * tid + 1] = kf.y;
        uint32_t hw, lw;
        split2(kf.x, kf.y, hw, lw);
        kpk[(size_t)m * 100 + tid] = make_uint2(hw, lw);
        int x = qi + NUMQ * rr[m];
        float2 vf = *(const float2*)&v_emb[(size_t)x * DIMS + 2 * tid];
        split2(vf.x, vf.y, hw, lw);
        vpk[(size_t)m * 100 + tid] = make_uint2(hw, lw);
    }
    __syncthreads();

    if (tid < 200) {
        int s = tid >> 2, g = tid & 3;
        const float* mk = Mk + s * DIMS + g * 50;
        const float* kr = krow + g * 50;
        float acc = 0.f;
        #pragma unroll 10
        for (int kk = 0; kk < 50; ++kk) acc = fmaf(kr[kk], __ldg(&mk[kk]), acc);
        part4[tid] = acc;
    }
    __syncthreads();
    if (tid < SIZEM)
        logits[tid] = part4[4 * tid] + part4[4 * tid + 1] + part4[4 * tid + 2] + part4[4 * tid + 3];
    __syncthreads();
    if (tid < 32) {
        float v = logits[tid];
        if (tid + 32 < SIZEM) v = fmaxf(v, logits[tid + 32]);
        #pragma unroll
        for (int o = 16; o > 0; o >>= 1) v = fmaxf(v, __shfl_xor_sync(0xffffffff, v, o));
        if (tid == 0) sm_max = v;
    }
    __syncthreads();
    if (tid < SIZEM) logits[tid] = expf(logits[tid] - sm_max);
    __syncthreads();
    if (tid < 32) {
        float v = (tid < SIZEM) ? logits[tid] : 0.f;
        if (tid + 32 < SIZEM) v += logits[tid + 32];
        #pragma unroll
        for (int o = 16; o > 0; o >>= 1) v += __shfl_xor_sync(0xffffffff, v, o);
        if (tid == 0) sm_sum = v;
    }
    __syncthreads();
    if (tid < SIZEM) wOut[(size_t)m * SIZEM + tid] = logits[tid] / sm_sum;
}

// ---------------- memory scan (round-12 proven version) ----------------
__global__ void __launch_bounds__(512)
scan_kernel(const float* __restrict__ w,
            const float* __restrict__ e,
            const float* __restrict__ a,
            const float* __restrict__ Mv0,
            float* __restrict__ MvOut,
            uint2* __restrict__ readPk)
{
    const int cs = blockIdx.x;            // 0..1
    const int b  = blockIdx.y;
    const int j0 = cs * 100;
    __shared__ __align__(16) float ebuf[4][100];
    __shared__ __align__(16) float abuf[4][100];
    __shared__ __align__(16) float wbuf[4][52];
    __shared__ float part[2][1000];
    const int tid = threadIdx.x;          // 512

    const int sg = tid / 50;              // 0..9 for tid<500
    const int jj = tid % 50;
    const int s0 = sg * 5;

    float st0[5], st1[5];
    if (tid < 500) {
        #pragma unroll
        for (int i = 0; i < 5; ++i) {
            float2 v = *(const float2*)&Mv0[(s0 + i) * DIMS + j0 + 2 * jj];
            st0[i] = v.x; st1[i] = v.y;
        }
    }

    #define SCAN_STAGE(tt) do {                                                         \
        int _slot = (tt) & 3;                                                           \
        if (tid < 25) {                                                                 \
            cp16((uint32_t)__cvta_generic_to_shared(&ebuf[_slot][tid * 4]),             \
                 e + ((size_t)b * DIMS + (tt)) * DIMS + j0 + tid * 4);                  \
        } else if (tid < 50) {                                                          \
            int _q = tid - 25;                                                          \
            cp16((uint32_t)__cvta_generic_to_shared(&abuf[_slot][_q * 4]),              \
                 a + ((size_t)b * DIMS + (tt)) * DIMS + j0 + _q * 4);                   \
        } else if (tid < 75) {                                                          \
            int _q = tid - 50;                                                          \
            cp8((uint32_t)__cvta_generic_to_shared(&wbuf[_slot][_q * 2]),               \
                w + ((size_t)b * DIMS + (tt)) * SIZEM + _q * 2);                        \
        }                                                                               \
    } while (0)

    SCAN_STAGE(0); CP_COMMIT;
    SCAN_STAGE(1); CP_COMMIT;

    for (int t = 0; t < DIMS; ++t) {
        const int cur = t & 3;
        if (t + 2 < DIMS) SCAN_STAGE(t + 2);
        CP_COMMIT;
        asm volatile("cp.async.wait_group 2;" ::: "memory");
        __syncthreads();

        if (tid < 500) {
            float2 ev = *(const float2*)&ebuf[cur][2 * jj];
            float2 av = *(const float2*)&abuf[cur][2 * jj];
            float acc0 = 0.f, acc1 = 0.f;
            float* outb = MvOut + ((size_t)(b * (DIMS + 1) + t) * SIZEM) * DIMS + j0 + 2 * jj;
            #pragma unroll
            for (int i = 0; i < 5; ++i) {
                float wv = wbuf[cur][s0 + i];
                float m0 = st0[i], m1 = st1[i];
                float2 o; o.x = m0; o.y = m1;
                *(float2*)(outb + (size_t)(s0 + i) * DIMS) = o;
                acc0 = fmaf(wv, m0, acc0);
                acc1 = fmaf(wv, m1, acc1);
                st0[i] = fmaf(wv, fmaf(-ev.x, m0, av.x), m0);
                st1[i] = fmaf(wv, fmaf(-ev.y, m1, av.y), m1);
            }
            float2 pp; pp.x = acc0; pp.y = acc1;
            *(float2*)&part[t & 1][sg * 100 + 2 * jj] = pp;
        }
        if (t > 0 && tid < 50) {
            const float* pv = part[(t - 1) & 1];
            float s0v = 0.f, s1v = 0.f;
            #pragma unroll
            for (int g = 0; g < 10; ++g) {
                float2 p2v = *(const float2*)&pv[g * 100 + 2 * tid];
                s0v += p2v.x; s1v += p2v.y;
            }
            uint32_t hw, lw;
            split2(s0v, s1v, hw, lw);
            readPk[((size_t)b * DIMS + (t - 1)) * 100 + (j0 >> 1) + tid] = make_uint2(hw, lw);
        }
    }
    __syncthreads();
    if (tid < 50) {
        const float* pv = part[199 & 1];
        float s0v = 0.f, s1v = 0.f;
        #pragma unroll
        for (int g = 0; g < 10; ++g) {
            float2 p2v = *(const float2*)&pv[g * 100 + 2 * tid];
            s0v += p2v.x; s1v += p2v.y;
        }
        uint32_t hw, lw;
        split2(s0v, s1v, hw, lw);
        readPk[((size_t)b * DIMS + 199) * 100 + (j0 >> 1) + tid] = make_uint2(hw, lw);
    }
    if (tid < 500) {
        #pragma unroll
        for (int i = 0; i < 5; ++i) {
            float2 o; o.x = st0[i]; o.y = st1[i];
            *(float2*)&MvOut[((size_t)(b * (DIMS + 1) + DIMS) * SIZEM + s0 + i) * DIMS + j0 + 2 * jj] = o;
        }
    }
    #undef SCAN_STAGE
}

// ---------------- p2 partials ----------------
__global__ void p2_kernel(const float* __restrict__ fl, const float* __restrict__ Wp,
                          float* __restrict__ p2part)
{
    int b = blockIdx.x, part = blockIdx.y;
    int t = threadIdx.x;
    if (t >= DIMS) return;
    const float* base = fl + (size_t)b * DIMS * DIMS + (size_t)part * 50 * DIMS + t;
    const float* wp = Wp + DIMS + part * 50;
    float a0 = 0.f, a1 = 0.f;
    #pragma unroll
    for (int c = 0; c < 50; c += 2) {
        a0 = fmaf(__ldg(&wp[c]),     base[(size_t)c * DIMS],       a0);
        a1 = fmaf(__ldg(&wp[c + 1]), base[(size_t)(c + 1) * DIMS], a1);
    }
    p2part[((size_t)b * 4 + part) * DIMS + t] = a0 + a1;
}

// ---------------- final p ----------------
__global__ void p_kernel(const float* __restrict__ f, const float* __restrict__ p2part,
                         const float* __restrict__ Wp, const float* __restrict__ bp,
                         float* __restrict__ pOut)
{
    int bt = blockIdx.x;
    int b  = bt / DIMS, t = bt % DIMS;
    int tid = threadIdx.x;                // 128
    float acc = 0.f;
    for (int c = tid; c < DIMS; c += 128)
        acc = fmaf(__ldg(&Wp[c]), f[(size_t)bt * DIMS + c], acc);
    __shared__ float red[128];
    red[tid] = acc;
    __syncthreads();
    #pragma unroll
    for (int s = 64; s > 0; s >>= 1) {
        if (tid < s) red[tid] += red[tid + s];
        __syncthreads();
    }
    if (tid == 0) {
        float p2 = p2part[((size_t)b * 4 + 0) * DIMS + t] + p2part[((size_t)b * 4 + 1) * DIMS + t]
                 + p2part[((size_t)b * 4 + 2) * DIMS + t] + p2part[((size_t)b * 4 + 3) * DIMS + t];
        pOut[bt] = 1.f / (1.f + expf(-(red[0] + p2 + bp[0])));
    }
}

// ---------------- launcher ----------------
extern "C" void kernel_launch(void* const* d_in, const int* in_sizes, int n_in,
                              void* d_out, int out_size)
{
    const int*   q     = (const int*)d_in[0];
    const int*   r     = (const int*)d_in[1];
    const float* bert  = (const float*)d_in[2];
    const float* k_emb = (const float*)d_in[3];
    const float* v_emb = (const float*)d_in[4];
    const float* Mk    = (const float*)d_in[5];
    const float* Mv0   = (const float*)d_in[6];
    const float* W_at  = (const float*)d_in[7];
    const float* b_at  = (const float*)d_in[8];
    const float* W_at2 = (const float*)d_in[9];
    const float* b_at2 = (const float*)d_in[10];
    const float* W_fus = (const float*)d_in[11];
    const float* b_fus = (const float*)d_in[12];
    const float* W_e   = (const float*)d_in[13];
    const float* b_e   = (const float*)d_in[14];
    const float* W_a   = (const float*)d_in[15];
    const float* b_a   = (const float*)d_in[16];
    const float* W_f   = (const float*)d_in[17];
    const float* b_f   = (const float*)d_in[18];
    const float* W_p   = (const float*)d_in[19];
    const float* b_p   = (const float*)d_in[20];

    float* out    = (float*)d_out;
    float* p_out  = out + OFF_P;
    float* mv_out = out + OFF_MV;
    float* w_out  = out + OFF_W;

    uint2 *T1p, *ematp, *kp, *vp, *readp;
    float *eb, *ab, *fb, *flb, *p2b;
    cudaGetSymbolAddress((void**)&T1p,   g_T1);
    cudaGetSymbolAddress((void**)&ematp, g_emat);
    cudaGetSymbolAddress((void**)&kp,    g_k);
    cudaGetSymbolAddress((void**)&vp,    g_v);
    cudaGetSymbolAddress((void**)&eb,    g_e);
    cudaGetSymbolAddress((void**)&ab,    g_a);
    cudaGetSymbolAddress((void**)&readp, g_read);
    cudaGetSymbolAddress((void**)&fb,    g_f);
    cudaGetSymbolAddress((void**)&flb,   g_fl);
    cudaGetSymbolAddress((void**)&p2b,   g_p2);

    uint4 *pw_at, *pw_at2, *pw_e, *pw_a, *pw_f, *pw_fus;
    cudaGetSymbolAddress((void**)&pw_at,  g_pw_at);
    cudaGetSymbolAddress((void**)&pw_at2, g_pw_at2);
    cudaGetSymbolAddress((void**)&pw_e,   g_pw_e);
    cudaGetSymbolAddress((void**)&pw_a,   g_pw_a);
    cudaGetSymbolAddress((void**)&pw_f,   g_pw_f);
    cudaGetSymbolAddress((void**)&pw_fus, g_pw_fus);

    cudaFuncSetAttribute((const void*)tgemm<0,1>, cudaFuncAttributeMaxDynamicSharedMemorySize, GEMM_SMEM);
    cudaFuncSetAttribute((const void*)tgemm<2,1>, cudaFuncAttributeMaxDynamicSharedMemorySize, GEMM_SMEM);
    cudaFuncSetAttribute((const void*)tgemm<3,1>, cudaFuncAttributeMaxDynamicSharedMemorySize, GEMM_SMEM);
    cudaFuncSetAttribute((const void*)tgemm<4,0>, cudaFuncAttributeMaxDynamicSharedMemorySize, GEMM_SMEM);
    cudaFuncSetAttribute((const void*)tgemm<5,1>, cudaFuncAttributeMaxDynamicSharedMemorySize, GEMM_SMEM);

    const int MR = BATCH * DIMS;          // 12800
    cudaStream_t s0 = 0;
    cudaStream_t sB = g_sp.sB;

    // ---- prep all weights, then fork ----
    prep_all<<<500, 256, 0, s0>>>(W_at, W_at2, W_e, W_a, W_f, W_fus,
                                  pw_at, pw_at2, pw_e, pw_a, pw_f, pw_fus);
    cudaEventRecord(g_sp.evFork, s0);
    cudaStreamWaitEvent(sB, g_sp.evFork, 0);

    // ---- chain B on sB: wk/gather -> e,a ----
    wk_gather_kernel<<<MR, 256, 0, sB>>>(q, r, k_emb, v_emb, Mk, w_out, kp, vp);
    tgemm<5,1><<<dim3(2, 100, 2), 256, GEMM_SMEM, sB>>>(vp, nullptr, pw_e, pw_a, b_e, b_a,
                                                        eb, ab, DIMS, DIMS, 7);
    cudaEventRecord(g_sp.evB, sB);

    // ---- chain A on s0: T1 (fp32 A) -> em_at (packed A) ----
    tgemm<4,0><<<dim3(2, 256), 256, GEMM_SMEM, s0>>>(bert, nullptr, pw_at, nullptr, b_at, nullptr,
                                                     (float*)T1p, nullptr, HBERT, HBERT, 24);
    tgemm<0,1><<<dim3(2, 100), 256, GEMM_SMEM, s0>>>(T1p, nullptr, pw_at2, nullptr, b_at2, nullptr,
                                                     (float*)ematp, nullptr, LBERT, LBERT, 16);
    cudaEventRecord(g_sp.evA2, s0);

    // ---- sB: fl + p2 overlap with scan ----
    cudaStreamWaitEvent(sB, g_sp.evA2, 0);
    tgemm<3,1><<<dim3(2, 100), 256, GEMM_SMEM, sB>>>(vp, ematp, pw_fus, nullptr, b_fus, nullptr,
                                                     flb, nullptr, 2 * DIMS, DIMS, 13);
    p2_kernel<<<dim3(BATCH, 4), 256, 0, sB>>>(flb, W_p, p2b);
    cudaEventRecord(g_sp.evFl, sB);

    // ---- s0: scan (after e/a), then f, then p ----
    cudaStreamWaitEvent(s0, g_sp.evB, 0);
    scan_kernel<<<dim3(2, BATCH), 512, 0, s0>>>(w_out, eb, ab, Mv0, mv_out, readp);
    tgemm<2,1><<<dim3(2, 100), 256, GEMM_SMEM, s0>>>(readp, kp, pw_f, nullptr, b_f, nullptr,
                                                     fb, nullptr, 2 * DIMS, DIMS, 13);
    cudaStreamWaitEvent(s0, g_sp.evFl, 0);
    p_kernel<<<MR, 128, 0, s0>>>(fb, p2b, W_p, b_p, p_out);
}